// round 4
// baseline (speedup 1.0000x reference)
#include <cuda_runtime.h>
#include <cstdint>

// LinearSelfAttention via mma.sync tf32 GEMMs (tcgen05 unavailable: harness
// PTX target is sm_103 without the 'a' feature suffix).
// out = H + ((P G Q - u v^T) H) / n,  G = H H^T, u = P h_n, v = Q^T h_n.

#define RDIM 257
#define NCOL 2049
#define NBAT 16
#define INV_N (1.0f / 2048.0f)

__device__ float g_G[NBAT][RDIM * RDIM];
__device__ float g_T[NBAT][RDIM * RDIM];
__device__ float g_W[NBAT][RDIM * RDIM];
__device__ float g_u[NBAT][RDIM];
__device__ float g_v[NBAT][RDIM];

// ---------------------------------------------------------------------------
__device__ __forceinline__ uint32_t smem_u32(const void* p) {
    uint32_t a;
    asm("{ .reg .u64 t; cvta.to.shared.u64 t, %1; cvt.u32.u64 %0, t; }"
        : "=r"(a) : "l"(p));
    return a;
}

__device__ __forceinline__ void cp4(void* s, const void* g) {
    uint32_t sa = smem_u32(s);
    asm volatile("cp.async.ca.shared.global [%0], [%1], 4;"
                 :: "r"(sa), "l"(g) : "memory");
}
#define CP_COMMIT() asm volatile("cp.async.commit_group;" ::: "memory")
#define CP_WAIT0()  asm volatile("cp.async.wait_group 0;" ::: "memory")

// m16n8k8 tf32: D += A * B  (fp32 inputs: HW uses tf32 bits = truncation)
__device__ __forceinline__ void mma8(float* c, const uint32_t* a,
                                     const uint32_t* b) {
    asm volatile(
        "mma.sync.aligned.m16n8k8.row.col.f32.tf32.tf32.f32 "
        "{%0,%1,%2,%3}, {%4,%5,%6,%7}, {%8,%9}, {%0,%1,%2,%3};"
        : "+f"(c[0]), "+f"(c[1]), "+f"(c[2]), "+f"(c[3])
        : "r"(a[0]), "r"(a[1]), "r"(a[2]), "r"(a[3]), "r"(b[0]), "r"(b[1]));
}

// ---------------------------------------------------------------------------
// SMEM tile loaders (cp.async 4B, zero-fill OOB via direct STS)
// A-style: dst[m][k] (stride 33), global row-major [r][k], k contiguous.
// ---------------------------------------------------------------------------
__device__ __forceinline__ void loadA(float* dst, const float* __restrict__ g,
                                      int ld, int r0, int rmax, int k0,
                                      int kmax, int tid) {
    const int kk = tid & 31;
    const int mb = tid >> 5;
    const bool kin = (k0 + kk) < kmax;
    const float* gp = g + (size_t)r0 * ld + k0 + kk;
#pragma unroll
    for (int i = 0; i < 16; i++) {
        int m = mb + (i << 3);
        float* s = dst + m * 33 + kk;
        if (kin && (r0 + m) < rmax) cp4(s, gp + (size_t)m * ld);
        else *s = 0.0f;
    }
}

// B-style (NN): dst[k][n] (stride 132), global row-major [k][n], n contiguous.
__device__ __forceinline__ void loadB(float* dst, const float* __restrict__ g,
                                      int ld, int n0, int nmax, int k0,
                                      int kmax, int tid) {
    const int nn = tid & 127;
    const int kb = tid >> 7;  // 0..1
    const bool nin = (n0 + nn) < nmax;
    const float* gp = g + (size_t)k0 * ld + n0 + nn;
#pragma unroll
    for (int i = 0; i < 16; i++) {
        int k = kb + (i << 1);
        float* s = dst + k * 132 + nn;
        if (nin && (k0 + k) < kmax) cp4(s, gp + (size_t)k * ld);
        else *s = 0.0f;
    }
}

// ---------------------------------------------------------------------------
// Generic NT/NN tf32 GEMM: C = epi( sum_k A[m,k] * Bop[k,n] )
//  TRANSB=true : B global is [n][k] (k contiguous)   -> NT
//  TRANSB=false: B global is [k][n] (n contiguous)   -> NN
//  MODE 0: C = acc
//  MODE 1: C = acc - u[row] v[col]
//  MODE 2: C = E[idx] + acc * INV_N
// CTA tile 128x128, BK=32, 256 thr, warp tile 32x64.
// ---------------------------------------------------------------------------
#define BUF_F 4224  // floats per buffer (128*33 == 32*132)
#define SMEM_BYTES (4 * BUF_F * 4)

template <int MODE, bool TRANSB>
__global__ void __launch_bounds__(256)
k_gemm(const float* __restrict__ A, size_t sA, int lda,
       const float* __restrict__ B, size_t sB, int ldb,
       float* __restrict__ C, size_t sC, int ldc,
       int M, int N, int K, const float* __restrict__ E) {
    extern __shared__ float sm[];
    float* As = sm;               // 2 buffers
    float* Bs = sm + 2 * BUF_F;   // 2 buffers

    const int tid = threadIdx.x;
    const int b = blockIdx.z;
    const int m0 = blockIdx.y * 128, n0 = blockIdx.x * 128;
    const float* Ab = A + (size_t)b * sA;
    const float* Bb = B + (size_t)b * sB;
    float* Cb = C + (size_t)b * sC;

    const int lane = tid & 31, wid = tid >> 5;
    const int wm = (wid & 3) * 32;   // warp m offset
    const int wn = (wid >> 2) * 64;  // warp n offset
    const int g = lane >> 2, tg = lane & 3;

    float acc[2][8][4];
#pragma unroll
    for (int i = 0; i < 2; i++)
#pragma unroll
        for (int j = 0; j < 8; j++)
#pragma unroll
            for (int r = 0; r < 4; r++) acc[i][j][r] = 0.0f;

    const int nc = (K + 31) >> 5;

    loadA(As, Ab, lda, m0, M, 0, K, tid);
    if (TRANSB) loadA(Bs, Bb, ldb, n0, N, 0, K, tid);
    else        loadB(Bs, Bb, ldb, n0, N, 0, K, tid);
    CP_COMMIT();

    for (int c = 0; c < nc; c++) {
        CP_WAIT0();
        __syncthreads();
        if (c + 1 < nc) {
            const int k0 = (c + 1) << 5;
            const int nb = (c + 1) & 1;
            loadA(As + nb * BUF_F, Ab, lda, m0, M, k0, K, tid);
            if (TRANSB) loadA(Bs + nb * BUF_F, Bb, ldb, n0, N, k0, K, tid);
            else        loadB(Bs + nb * BUF_F, Bb, ldb, n0, N, k0, K, tid);
            CP_COMMIT();
        }
        const float* As_ = As + (c & 1) * BUF_F;
        const float* Bs_ = Bs + (c & 1) * BUF_F;
#pragma unroll
        for (int ks = 0; ks < 4; ks++) {
            const int k = ks * 8;
            uint32_t a[2][4], bf[8][2];
#pragma unroll
            for (int mt = 0; mt < 2; mt++) {
                const int r = wm + mt * 16 + g;
                a[mt][0] = __float_as_uint(As_[r * 33 + k + tg]);
                a[mt][1] = __float_as_uint(As_[(r + 8) * 33 + k + tg]);
                a[mt][2] = __float_as_uint(As_[r * 33 + k + tg + 4]);
                a[mt][3] = __float_as_uint(As_[(r + 8) * 33 + k + tg + 4]);
            }
#pragma unroll
            for (int nt = 0; nt < 8; nt++) {
                const int cn = wn + nt * 8 + g;
                if (TRANSB) {
                    bf[nt][0] = __float_as_uint(Bs_[cn * 33 + k + tg]);
                    bf[nt][1] = __float_as_uint(Bs_[cn * 33 + k + tg + 4]);
                } else {
                    bf[nt][0] = __float_as_uint(Bs_[(k + tg) * 132 + cn]);
                    bf[nt][1] = __float_as_uint(Bs_[(k + tg + 4) * 132 + cn]);
                }
            }
#pragma unroll
            for (int mt = 0; mt < 2; mt++)
#pragma unroll
                for (int nt = 0; nt < 8; nt++) mma8(acc[mt][nt], a[mt], bf[nt]);
        }
        __syncthreads();
    }

    // epilogue (direct from accumulators)
#pragma unroll
    for (int mt = 0; mt < 2; mt++) {
        const int row0 = m0 + wm + mt * 16 + g;
#pragma unroll
        for (int half = 0; half < 2; half++) {
            const int row = row0 + half * 8;
            if (row >= M) continue;
            float uu = 0.0f;
            if (MODE == 1) uu = g_u[b][row];
#pragma unroll
            for (int nt = 0; nt < 8; nt++) {
                const int col = n0 + wn + nt * 8 + tg * 2;
                const float v0 = acc[mt][nt][half * 2 + 0];
                const float v1 = acc[mt][nt][half * 2 + 1];
                const size_t idx = (size_t)row * ldc + col;
                if (MODE == 0) {
                    if (col < N) Cb[idx] = v0;
                    if (col + 1 < N) Cb[idx + 1] = v1;
                } else if (MODE == 1) {
                    if (col < N) Cb[idx] = v0 - uu * g_v[b][col];
                    if (col + 1 < N) Cb[idx + 1] = v1 - uu * g_v[b][col + 1];
                } else {
                    const float* Eb = E + (size_t)b * sC;
                    if (col < N) Cb[idx] = Eb[idx] + v0 * INV_N;
                    if (col + 1 < N) Cb[idx + 1] = Eb[idx + 1] + v1 * INV_N;
                }
            }
        }
    }
}

// ---------------------------------------------------------------------------
// u_b = P h_n,  v_b = Q^T h_n   (exact fp32, tiny)
// ---------------------------------------------------------------------------
__global__ void k_uv(const float* __restrict__ H, const float* __restrict__ P,
                     const float* __restrict__ Q) {
    const int b = blockIdx.x;
    const float* __restrict__ Hb = H + (size_t)b * RDIM * NCOL;
    __shared__ float hn[RDIM];
    for (int e = threadIdx.x; e < RDIM; e += blockDim.x)
        hn[e] = Hb[(size_t)e * NCOL + (NCOL - 1)];
    __syncthreads();
    for (int i = threadIdx.x; i < RDIM; i += blockDim.x) {
        float su = 0.0f, sv = 0.0f;
        for (int e = 0; e < RDIM; e++) {
            su += P[i * RDIM + e] * hn[e];
            sv += hn[e] * Q[e * RDIM + i];
        }
        g_u[b][i] = su;
        g_v[b][i] = sv;
    }
}

// ---------------------------------------------------------------------------
extern "C" void kernel_launch(void* const* d_in, const int* in_sizes, int n_in,
                              void* d_out, int out_size) {
    const float* H = (const float*)d_in[0];
    const float* P = (const float*)d_in[1];
    const float* Q = (const float*)d_in[2];
    float* out = (float*)d_out;

    cudaFuncSetAttribute(k_gemm<0, true>,
                         cudaFuncAttributeMaxDynamicSharedMemorySize, SMEM_BYTES);
    cudaFuncSetAttribute(k_gemm<0, false>,
                         cudaFuncAttributeMaxDynamicSharedMemorySize, SMEM_BYTES);
    cudaFuncSetAttribute(k_gemm<1, false>,
                         cudaFuncAttributeMaxDynamicSharedMemorySize, SMEM_BYTES);
    cudaFuncSetAttribute(k_gemm<2, false>,
                         cudaFuncAttributeMaxDynamicSharedMemorySize, SMEM_BYTES);

    float *Gm, *Tm, *Wm;
    cudaGetSymbolAddress((void**)&Gm, g_G);
    cudaGetSymbolAddress((void**)&Tm, g_T);
    cudaGetSymbolAddress((void**)&Wm, g_W);

    const size_t HB = (size_t)RDIM * NCOL;
    const size_t GB = (size_t)RDIM * RDIM;

    k_uv<<<NBAT, 288>>>(H, P, Q);

    // G = H H^T : M=N=257, K=2049  (NT)
    k_gemm<0, true><<<dim3(3, 3, NBAT), 256, SMEM_BYTES>>>(
        H, HB, NCOL, H, HB, NCOL, Gm, GB, RDIM, RDIM, RDIM, NCOL, nullptr);
    // T = G Q : M=N=K=257  (NN)
    k_gemm<0, false><<<dim3(3, 3, NBAT), 256, SMEM_BYTES>>>(
        Gm, GB, RDIM, Q, 0, RDIM, Tm, GB, RDIM, RDIM, RDIM, RDIM, nullptr);
    // W = P T - u v^T : M=N=K=257  (NN, rank-1 fused)
    k_gemm<1, false><<<dim3(3, 3, NBAT), 256, SMEM_BYTES>>>(
        P, 0, RDIM, Tm, GB, RDIM, Wm, GB, RDIM, RDIM, RDIM, RDIM, nullptr);
    // out = H + (W H)/n : M=257, N=2049, K=257  (NN, residual fused)
    k_gemm<2, false><<<dim3(17, 3, NBAT), 256, SMEM_BYTES>>>(
        Wm, GB, RDIM, H, HB, NCOL, out, HB, NCOL, RDIM, NCOL, RDIM, H);
}

// round 5
// speedup vs baseline: 1.9366x; 1.9366x over previous
#include <cuda_runtime.h>
#include <cstdint>

// LinearSelfAttention via mma.sync tf32 GEMMs with padded operands.
// out = H + ((P G Q - u v^T) H) / n,  G = H H^T, u = P h_n, v = Q^T h_n.
// All operands are pre-padded to 16B-aligned, zero-filled buffers so every
// GEMM tile load is a guard-free 16-byte cp.async.

#define RDIM 257
#define NCOL 2049
#define NBAT 16
#define INV_N (1.0f / 2048.0f)

#define MP   384    // padded row dim (3 x 128 tiles)
#define KH   2208   // Hp leading dim (covers 17*128=2176 cols + slack, 16B-div)
#define KHC  2080   // k-extent for stage 1 (65 chunks of 32 >= 2049)
#define LDP  384    // scratch leading dim
#define KS   288    // k-extent for K=257 stages (9 chunks of 32)

__device__ float g_Hp[NBAT][MP * KH];   // padded H
__device__ float g_Pp[MP * LDP];        // padded P
__device__ float g_Qp[MP * LDP];        // padded Q
__device__ float g_G[NBAT][MP * LDP];
__device__ float g_T[NBAT][MP * LDP];
__device__ float g_W[NBAT][MP * LDP];
__device__ float g_u[NBAT][MP];         // pads stay 0 (static zero-init)
__device__ float g_v[NBAT][MP];

// ---------------------------------------------------------------------------
__device__ __forceinline__ uint32_t smem_u32(const void* p) {
    uint32_t a;
    asm("{ .reg .u64 t; cvta.to.shared.u64 t, %1; cvt.u32.u64 %0, t; }"
        : "=r"(a) : "l"(p));
    return a;
}

__device__ __forceinline__ void cp16(void* s, const void* g) {
    uint32_t sa = smem_u32(s);
    asm volatile("cp.async.cg.shared.global [%0], [%1], 16;"
                 :: "r"(sa), "l"(g) : "memory");
}
#define CP_COMMIT() asm volatile("cp.async.commit_group;" ::: "memory")
#define CP_WAIT1()  asm volatile("cp.async.wait_group 1;" ::: "memory")

__device__ __forceinline__ void mma8(float* c, const uint32_t* a,
                                     const uint32_t* b) {
    asm volatile(
        "mma.sync.aligned.m16n8k8.row.col.f32.tf32.tf32.f32 "
        "{%0,%1,%2,%3}, {%4,%5,%6,%7}, {%8,%9}, {%0,%1,%2,%3};"
        : "+f"(c[0]), "+f"(c[1]), "+f"(c[2]), "+f"(c[3])
        : "r"(a[0]), "r"(a[1]), "r"(a[2]), "r"(a[3]), "r"(b[0]), "r"(b[1]));
}

// ---------------------------------------------------------------------------
// Vectorized guard-free tile loaders (sources are padded + zero-filled).
// A-style (K-major): dst[m][k], 128x32, smem stride 36 floats.
__device__ __forceinline__ void loadA_v(float* dst, const float* __restrict__ g,
                                        int ld, int r0, int k0, int tid) {
    const float* gp = g + (size_t)r0 * ld + k0;
    const int kk = (tid & 7) * 4;
    const int m = tid >> 3;
#pragma unroll
    for (int i = 0; i < 4; i++)
        cp16(dst + (m + i * 32) * 36 + kk, gp + (size_t)(m + i * 32) * ld + kk);
}

// B-style (NN): dst[k][n], 32x128, smem stride 136 floats.
__device__ __forceinline__ void loadB_v(float* dst, const float* __restrict__ g,
                                        int ld, int n0, int k0, int tid) {
    const float* gp = g + (size_t)k0 * ld + n0;
    const int nn = (tid & 31) * 4;
    const int k = tid >> 5;
#pragma unroll
    for (int i = 0; i < 4; i++)
        cp16(dst + (k + i * 8) * 136 + nn, gp + (size_t)(k + i * 8) * ld + nn);
}

// ---------------------------------------------------------------------------
// Generic tf32 GEMM. CTA 128x128, BK=32, 256 thr, warp 32x64, 3-stage pipe.
//  TRANSB: B global is [n][k] (NT) else [k][n] (NN).
//  MODE 0: C = acc            (unguarded, padded C)
//  MODE 1: C = acc - u[row] v[col]   (unguarded, padded C)
//  MODE 2: C = E + acc/n      (guarded by Mout/Nout, unpadded C)
// ---------------------------------------------------------------------------
#define ABUF 4608   // 128*36
#define BBUF 4608   // >= 32*136 and 128*36
#define SMEM_BYTES (6 * 4608 * 4)

template <int MODE, bool TRANSB>
__global__ void __launch_bounds__(256, 2)
k_gemm(const float* __restrict__ A, size_t sA, int lda,
       const float* __restrict__ B, size_t sB, int ldb,
       float* __restrict__ C, size_t sC, int ldc,
       int nc, int Mout, int Nout, const float* __restrict__ E, size_t sE) {
    extern __shared__ float sm[];
    float* As = sm;                 // 3 buffers of ABUF
    float* Bs = sm + 3 * ABUF;      // 3 buffers of BBUF

    const int tid = threadIdx.x;
    const int b = blockIdx.z;
    const int m0 = blockIdx.y * 128, n0 = blockIdx.x * 128;
    const float* Ab = A + (size_t)b * sA;
    const float* Bb = B + (size_t)b * sB;
    float* Cb = C + (size_t)b * sC;

    const int lane = tid & 31, wid = tid >> 5;
    const int wm = (wid & 3) * 32;
    const int wn = (wid >> 2) * 64;
    const int g = lane >> 2, tg = lane & 3;

    float acc[2][8][4];
#pragma unroll
    for (int i = 0; i < 2; i++)
#pragma unroll
        for (int j = 0; j < 8; j++)
#pragma unroll
            for (int r = 0; r < 4; r++) acc[i][j][r] = 0.0f;

    // prologue: prefetch chunks 0 and 1
#pragma unroll
    for (int c = 0; c < 2; c++) {
        loadA_v(As + c * ABUF, Ab, lda, m0, c * 32, tid);
        if (TRANSB) loadA_v(Bs + c * BBUF, Bb, ldb, n0, c * 32, tid);
        else        loadB_v(Bs + c * BBUF, Bb, ldb, n0, c * 32, tid);
        CP_COMMIT();
    }

    for (int c = 0; c < nc; c++) {
        CP_WAIT1();
        __syncthreads();
        if (c + 2 < nc) {
            const int nb = (c + 2) % 3;
            const int k0 = (c + 2) * 32;
            loadA_v(As + nb * ABUF, Ab, lda, m0, k0, tid);
            if (TRANSB) loadA_v(Bs + nb * BBUF, Bb, ldb, n0, k0, tid);
            else        loadB_v(Bs + nb * BBUF, Bb, ldb, n0, k0, tid);
        }
        CP_COMMIT();

        const float* As_ = As + (c % 3) * ABUF;
        const float* Bs_ = Bs + (c % 3) * BBUF;
#pragma unroll
        for (int ks = 0; ks < 4; ks++) {
            const int k = ks * 8;
            uint32_t a[2][4], bf[8][2];
#pragma unroll
            for (int mt = 0; mt < 2; mt++) {
                const int r = wm + mt * 16 + g;
                a[mt][0] = __float_as_uint(As_[r * 36 + k + tg]);
                a[mt][1] = __float_as_uint(As_[(r + 8) * 36 + k + tg]);
                a[mt][2] = __float_as_uint(As_[r * 36 + k + tg + 4]);
                a[mt][3] = __float_as_uint(As_[(r + 8) * 36 + k + tg + 4]);
            }
#pragma unroll
            for (int nt = 0; nt < 8; nt++) {
                const int cn = wn + nt * 8 + g;
                if (TRANSB) {
                    bf[nt][0] = __float_as_uint(Bs_[cn * 36 + k + tg]);
                    bf[nt][1] = __float_as_uint(Bs_[cn * 36 + k + tg + 4]);
                } else {
                    bf[nt][0] = __float_as_uint(Bs_[(k + tg) * 136 + cn]);
                    bf[nt][1] = __float_as_uint(Bs_[(k + tg + 4) * 136 + cn]);
                }
            }
#pragma unroll
            for (int mt = 0; mt < 2; mt++)
#pragma unroll
                for (int nt = 0; nt < 8; nt++) mma8(acc[mt][nt], a[mt], bf[nt]);
        }
        __syncthreads();
    }

    // epilogue
#pragma unroll
    for (int mt = 0; mt < 2; mt++) {
#pragma unroll
        for (int half = 0; half < 2; half++) {
            const int row = m0 + wm + mt * 16 + g + half * 8;
            if (MODE == 2 && row >= Mout) continue;
            float uu = 0.0f;
            if (MODE == 1) uu = g_u[b][row];
#pragma unroll
            for (int nt = 0; nt < 8; nt++) {
                const int col = n0 + wn + nt * 8 + tg * 2;
                const float v0 = acc[mt][nt][half * 2 + 0];
                const float v1 = acc[mt][nt][half * 2 + 1];
                const size_t idx = (size_t)row * ldc + col;
                if (MODE == 0) {
                    Cb[idx] = v0;
                    Cb[idx + 1] = v1;
                } else if (MODE == 1) {
                    Cb[idx] = v0 - uu * g_v[b][col];
                    Cb[idx + 1] = v1 - uu * g_v[b][col + 1];
                } else {
                    const float* Eb = E + (size_t)b * sE;
                    if (col < Nout) Cb[idx] = Eb[idx] + v0 * INV_N;
                    if (col + 1 < Nout) Cb[idx + 1] = Eb[idx + 1] + v1 * INV_N;
                }
            }
        }
    }
}

// ---------------------------------------------------------------------------
// padding kernels
// ---------------------------------------------------------------------------
__global__ void k_padH(const float* __restrict__ H) {
    const int b = blockIdx.y, r = blockIdx.x;
    const float* src = H + ((size_t)b * RDIM + r) * NCOL;
    float* dst = g_Hp[b] + (size_t)r * KH;
    const bool rv = r < RDIM;
    for (int c = threadIdx.x * 4; c < KH; c += 256 * 4) {
        float4 v;
        v.x = (rv && c + 0 < NCOL) ? src[c + 0] : 0.0f;
        v.y = (rv && c + 1 < NCOL) ? src[c + 1] : 0.0f;
        v.z = (rv && c + 2 < NCOL) ? src[c + 2] : 0.0f;
        v.w = (rv && c + 3 < NCOL) ? src[c + 3] : 0.0f;
        *(float4*)(dst + c) = v;
    }
}

__global__ void k_padPQ(const float* __restrict__ P,
                        const float* __restrict__ Q) {
    const int r = blockIdx.x;
    const float* src = (blockIdx.y == 0 ? P : Q) + (size_t)r * RDIM;
    float* dst = (blockIdx.y == 0 ? g_Pp : g_Qp) + (size_t)r * LDP;
    const bool rv = r < RDIM;
    for (int c = threadIdx.x * 4; c < LDP; c += 128 * 4) {
        float4 v;
        v.x = (rv && c + 0 < RDIM) ? src[c + 0] : 0.0f;
        v.y = (rv && c + 1 < RDIM) ? src[c + 1] : 0.0f;
        v.z = (rv && c + 2 < RDIM) ? src[c + 2] : 0.0f;
        v.w = (rv && c + 3 < RDIM) ? src[c + 3] : 0.0f;
        *(float4*)(dst + c) = v;
    }
}

// ---------------------------------------------------------------------------
// u_b = P h_n,  v_b = Q^T h_n   (exact fp32; pads of g_u/g_v never written)
// ---------------------------------------------------------------------------
__global__ void k_uv(const float* __restrict__ H, const float* __restrict__ P,
                     const float* __restrict__ Q) {
    const int b = blockIdx.x;
    const float* __restrict__ Hb = H + (size_t)b * RDIM * NCOL;
    __shared__ float hn[RDIM];
    for (int e = threadIdx.x; e < RDIM; e += blockDim.x)
        hn[e] = Hb[(size_t)e * NCOL + (NCOL - 1)];
    __syncthreads();
    for (int i = threadIdx.x; i < RDIM; i += blockDim.x) {
        float su = 0.0f, sv = 0.0f;
        for (int e = 0; e < RDIM; e++) {
            su += P[i * RDIM + e] * hn[e];
            sv += hn[e] * Q[e * RDIM + i];
        }
        g_u[b][i] = su;
        g_v[b][i] = sv;
    }
}

// ---------------------------------------------------------------------------
extern "C" void kernel_launch(void* const* d_in, const int* in_sizes, int n_in,
                              void* d_out, int out_size) {
    const float* H = (const float*)d_in[0];
    const float* P = (const float*)d_in[1];
    const float* Q = (const float*)d_in[2];
    float* out = (float*)d_out;

    cudaFuncSetAttribute(k_gemm<0, true>,
                         cudaFuncAttributeMaxDynamicSharedMemorySize, SMEM_BYTES);
    cudaFuncSetAttribute(k_gemm<0, false>,
                         cudaFuncAttributeMaxDynamicSharedMemorySize, SMEM_BYTES);
    cudaFuncSetAttribute(k_gemm<1, false>,
                         cudaFuncAttributeMaxDynamicSharedMemorySize, SMEM_BYTES);
    cudaFuncSetAttribute(k_gemm<2, false>,
                         cudaFuncAttributeMaxDynamicSharedMemorySize, SMEM_BYTES);

    float *Hp, *Pp, *Qp, *Gm, *Tm, *Wm;
    cudaGetSymbolAddress((void**)&Hp, g_Hp);
    cudaGetSymbolAddress((void**)&Pp, g_Pp);
    cudaGetSymbolAddress((void**)&Qp, g_Qp);
    cudaGetSymbolAddress((void**)&Gm, g_G);
    cudaGetSymbolAddress((void**)&Tm, g_T);
    cudaGetSymbolAddress((void**)&Wm, g_W);

    const size_t HPB = (size_t)MP * KH;   // padded H per-batch stride
    const size_t GB = (size_t)MP * LDP;   // scratch per-batch stride
    const size_t HB = (size_t)RDIM * NCOL;

    k_padH<<<dim3(MP, NBAT), 256>>>(H);
    k_padPQ<<<dim3(MP, 2), 128>>>(P, Q);
    k_uv<<<NBAT, 288>>>(H, P, Q);

    // G = Hp Hp^T : K=2080 (65 chunks), NT
    k_gemm<0, true><<<dim3(3, 3, NBAT), 256, SMEM_BYTES>>>(
        Hp, HPB, KH, Hp, HPB, KH, Gm, GB, LDP, KHC / 32, 0, 0, nullptr, 0);
    // T = G Qp : K=288 (9 chunks), NN
    k_gemm<0, false><<<dim3(3, 3, NBAT), 256, SMEM_BYTES>>>(
        Gm, GB, LDP, Qp, 0, LDP, Tm, GB, LDP, KS / 32, 0, 0, nullptr, 0);
    // W = Pp T - u v^T : K=288, NN
    k_gemm<1, false><<<dim3(3, 3, NBAT), 256, SMEM_BYTES>>>(
        Pp, 0, LDP, Tm, GB, LDP, Wm, GB, LDP, KS / 32, 0, 0, nullptr, 0);
    // out = H + (W Hp)/n : K=288, NN, guarded writes to unpadded out
    k_gemm<2, false><<<dim3(17, 3, NBAT), 256, SMEM_BYTES>>>(
        Wm, GB, LDP, Hp, HPB, KH, out, HB, NCOL, KS / 32, RDIM, NCOL, H, HB);
}

// round 6
// speedup vs baseline: 2.6053x; 1.3453x over previous
#include <cuda_runtime.h>
#include <cuda_fp16.h>
#include <cstdint>

// LinearSelfAttention via fp16-in/fp32-acc mma.sync (m16n8k16), all-NT GEMMs.
// out = H + ((P G Q - u v^T) H) / n,  G = H H^T, u = P h_n, v = Q^T h_n.
// Chain (every GEMM is NT: C[m,n] = sum_k A[m,k] B[n,k], both K-major):
//   G  = Hp (x) Hp            (split-K x2, fp32 partials, reduce -> fp16)
//   T' = Qt (x) G             ( = (G Q)^T )
//   W  = Pp (x) T' - u v^T
//   out= H + (W (x) Htp)/n

#define RDIM 257
#define NCOL 2049
#define NBAT 16
#define INV_N (1.0f / 2048.0f)

#define MP   384     // padded row dim
#define KHP  2176    // Hp cols / Htp rows (17*128)
#define LDS_ 384     // small-matrix leading dim
#define GB_  ((size_t)MP * LDS_)
#define SPLITOFF ((size_t)NBAT * MP * LDS_)

__device__ __half g_Hp[NBAT][MP * KHP];    // padded H, fp16
__device__ __half g_Ht[NBAT][KHP * MP];    // padded H^T, fp16
__device__ __half g_Pp[MP * LDS_];
__device__ __half g_Qt[MP * LDS_];         // Q^T padded
__device__ float  g_Gp[2][NBAT][MP * LDS_];// split-K partials
__device__ __half g_G[NBAT][MP * LDS_];
__device__ __half g_Tt[NBAT][MP * LDS_];
__device__ __half g_W[NBAT][MP * LDS_];
__device__ float  g_u[NBAT][MP];           // pads stay 0
__device__ float  g_v[NBAT][MP];

// ---------------------------------------------------------------------------
__device__ __forceinline__ uint32_t smem_u32(const void* p) {
    uint32_t a;
    asm("{ .reg .u64 t; cvta.to.shared.u64 t, %1; cvt.u32.u64 %0, t; }"
        : "=r"(a) : "l"(p));
    return a;
}
__device__ __forceinline__ void cp16(void* s, const void* g) {
    uint32_t sa = smem_u32(s);
    asm volatile("cp.async.cg.shared.global [%0], [%1], 16;"
                 :: "r"(sa), "l"(g) : "memory");
}
#define CP_COMMIT() asm volatile("cp.async.commit_group;" ::: "memory")
#define CP_WAIT1()  asm volatile("cp.async.wait_group 1;" ::: "memory")

// m16n8k16 fp16 in / fp32 acc
__device__ __forceinline__ void mma16(float* c, const uint32_t* a,
                                      const uint32_t* b) {
    asm volatile(
        "mma.sync.aligned.m16n8k16.row.col.f32.f16.f16.f32 "
        "{%0,%1,%2,%3}, {%4,%5,%6,%7}, {%8,%9}, {%0,%1,%2,%3};"
        : "+f"(c[0]), "+f"(c[1]), "+f"(c[2]), "+f"(c[3])
        : "r"(a[0]), "r"(a[1]), "r"(a[2]), "r"(a[3]), "r"(b[0]), "r"(b[1]));
}

// K-major tile loader: 128 rows x 64 halfs, smem stride 72 halfs, cp16 x4/thr.
__device__ __forceinline__ void loadT(__half* dst, const __half* __restrict__ g,
                                      int ld, int r0, int k0, int tid) {
    const __half* gp = g + (size_t)r0 * ld + k0;
    const int kk = (tid & 7) * 8;
    const int r = tid >> 3;
#pragma unroll
    for (int i = 0; i < 4; i++)
        cp16(dst + (r + i * 32) * 72 + kk, gp + (size_t)(r + i * 32) * ld + kk);
}

// ---------------------------------------------------------------------------
// Generic NT fp16 GEMM. CTA 128x128, BK=64, 256 thr, warp 32x64, double-buf.
//  MODE 0: split-K stage-1: blockIdx.z = b*2+sp; C fp32 partial, unguarded
//  MODE 1: C fp16 = acc
//  MODE 2: C fp16 = acc - u[row] v[col]
//  MODE 3: C fp32 = E + acc/n, guarded by Mout/Nout
// ---------------------------------------------------------------------------
#define ABUF (128 * 72)               // halfs per buffer
#define SMEM_BYTES (4 * ABUF * 2)     // A0,A1,B0,B1 = 73728 B

template <int MODE>
__global__ void __launch_bounds__(256, 2)
k_gemm(const __half* __restrict__ A, size_t sA, int lda,
       const __half* __restrict__ B, size_t sB, int ldb,
       void* __restrict__ Cv, size_t sC, int ldc,
       int nc, int Mout, int Nout, const float* __restrict__ E, size_t sE) {
    extern __shared__ __half sm[];
    __half* As = sm;             // 2 buffers
    __half* Bs = sm + 2 * ABUF;  // 2 buffers

    const int tid = threadIdx.x;
    int b, c0, ncl;
    float* Cf = nullptr;
    __half* Ch = nullptr;
    if (MODE == 0) {
        b = blockIdx.z >> 1;
        const int sp = blockIdx.z & 1;
        c0 = sp * 17;
        ncl = sp ? 16 : 17;
        Cf = (float*)Cv + (size_t)sp * SPLITOFF + (size_t)b * sC;
    } else {
        b = blockIdx.z;
        c0 = 0;
        ncl = nc;
        if (MODE == 3) Cf = (float*)Cv + (size_t)b * sC;
        else           Ch = (__half*)Cv + (size_t)b * sC;
    }
    const int m0 = blockIdx.y * 128, n0 = blockIdx.x * 128;
    const __half* Ab = A + (size_t)b * sA;
    const __half* Bb = B + (size_t)b * sB;

    const int lane = tid & 31, wid = tid >> 5;
    const int wm = (wid & 3) * 32;
    const int wn = (wid >> 2) * 64;
    const int g = lane >> 2, tg = lane & 3;

    float acc[2][8][4];
#pragma unroll
    for (int i = 0; i < 2; i++)
#pragma unroll
        for (int j = 0; j < 8; j++)
#pragma unroll
            for (int r = 0; r < 4; r++) acc[i][j][r] = 0.0f;

    // prologue: chunk 0 -> buffer 0
    loadT(As, Ab, lda, m0, c0 * 64, tid);
    loadT(Bs, Bb, ldb, n0, c0 * 64, tid);
    CP_COMMIT();

    for (int c = 0; c < ncl; c++) {
        if (c + 1 < ncl) {
            const int nb = (c + 1) & 1;
            const int k0 = (c0 + c + 1) * 64;
            loadT(As + nb * ABUF, Ab, lda, m0, k0, tid);
            loadT(Bs + nb * ABUF, Bb, ldb, n0, k0, tid);
        }
        CP_COMMIT();
        CP_WAIT1();
        __syncthreads();

        const __half* As_ = As + (c & 1) * ABUF;
        const __half* Bs_ = Bs + (c & 1) * ABUF;
#pragma unroll
        for (int ks = 0; ks < 4; ks++) {
            const int k = ks * 16;
            uint32_t a[2][4], bf[8][2];
#pragma unroll
            for (int mt = 0; mt < 2; mt++) {
                const int r = wm + mt * 16 + g;
                a[mt][0] = *(const uint32_t*)&As_[r * 72 + k + 2 * tg];
                a[mt][1] = *(const uint32_t*)&As_[(r + 8) * 72 + k + 2 * tg];
                a[mt][2] = *(const uint32_t*)&As_[r * 72 + k + 2 * tg + 8];
                a[mt][3] = *(const uint32_t*)&As_[(r + 8) * 72 + k + 2 * tg + 8];
            }
#pragma unroll
            for (int nt = 0; nt < 8; nt++) {
                const int cn = wn + nt * 8 + g;
                bf[nt][0] = *(const uint32_t*)&Bs_[cn * 72 + k + 2 * tg];
                bf[nt][1] = *(const uint32_t*)&Bs_[cn * 72 + k + 2 * tg + 8];
            }
#pragma unroll
            for (int mt = 0; mt < 2; mt++)
#pragma unroll
                for (int nt = 0; nt < 8; nt++) mma16(acc[mt][nt], a[mt], bf[nt]);
        }
        __syncthreads();
    }

    // epilogue
#pragma unroll
    for (int mt = 0; mt < 2; mt++) {
#pragma unroll
        for (int half = 0; half < 2; half++) {
            const int row = m0 + wm + mt * 16 + g + half * 8;
            if (MODE == 3 && row >= Mout) continue;
            float uu = 0.0f;
            if (MODE == 2) uu = g_u[b][row];
#pragma unroll
            for (int nt = 0; nt < 8; nt++) {
                const int col = n0 + wn + nt * 8 + tg * 2;
                float v0 = acc[mt][nt][half * 2 + 0];
                float v1 = acc[mt][nt][half * 2 + 1];
                const size_t idx = (size_t)row * ldc + col;
                if (MODE == 0) {
                    Cf[idx] = v0;
                    Cf[idx + 1] = v1;
                } else if (MODE == 1) {
                    *(__half2*)&Ch[idx] = __floats2half2_rn(v0, v1);
                } else if (MODE == 2) {
                    v0 -= uu * g_v[b][col];
                    v1 -= uu * g_v[b][col + 1];
                    *(__half2*)&Ch[idx] = __floats2half2_rn(v0, v1);
                } else {
                    const float* Eb = E + (size_t)b * sE;
                    if (col < Nout) Cf[idx] = Eb[idx] + v0 * INV_N;
                    if (col + 1 < Nout) Cf[idx + 1] = Eb[idx + 1] + v1 * INV_N;
                }
            }
        }
    }
}

// ---------------------------------------------------------------------------
// split-K reduce: G = fp16(Gp[0] + Gp[1])
// ---------------------------------------------------------------------------
__global__ void k_reduce() {
    const size_t i = ((size_t)blockIdx.x * 256 + threadIdx.x) * 4;
    const float* a = &g_Gp[0][0][0];
    const float* bb = &g_Gp[1][0][0];
    __half* o = &g_G[0][0];
    float4 x = *(const float4*)(a + i);
    float4 y = *(const float4*)(bb + i);
    __half2 h0 = __floats2half2_rn(x.x + y.x, x.y + y.y);
    __half2 h1 = __floats2half2_rn(x.z + y.z, x.w + y.w);
    *(__half2*)(o + i) = h0;
    *(__half2*)(o + i + 2) = h1;
}

// ---------------------------------------------------------------------------
// pad H -> Hp (fp16) and Htp (fp16 transpose), zero-filled, one H read.
// grid (KHP/32, MP/32, NBAT), block (32,8)
// ---------------------------------------------------------------------------
__global__ void k_pad(const float* __restrict__ H) {
    __shared__ float t[32][33];
    const int b = blockIdx.z;
    const int c0 = blockIdx.x * 32;  // t-dim
    const int r0 = blockIdx.y * 32;  // d-dim
    const float* Hb = H + (size_t)b * RDIM * NCOL;
    const int tx = threadIdx.x, ty = threadIdx.y;
#pragma unroll
    for (int i = 0; i < 4; i++) {
        const int r = r0 + ty + i * 8, c = c0 + tx;
        float v = (r < RDIM && c < NCOL) ? Hb[(size_t)r * NCOL + c] : 0.0f;
        t[ty + i * 8][tx] = v;
        g_Hp[b][(size_t)r * KHP + c] = __float2half_rn(v);
    }
    __syncthreads();
#pragma unroll
    for (int i = 0; i < 4; i++) {
        const int c = c0 + ty + i * 8, r = r0 + tx;
        g_Ht[b][(size_t)c * MP + r] = __float2half_rn(t[tx][ty + i * 8]);
    }
}

// pad P -> Pp, Q^T -> Qt. grid (12,12), block (32,8)
__global__ void k_padPQ(const float* __restrict__ P,
                        const float* __restrict__ Q) {
    __shared__ float t[32][33];
    const int c0 = blockIdx.x * 32, r0 = blockIdx.y * 32;
    const int tx = threadIdx.x, ty = threadIdx.y;
#pragma unroll
    for (int i = 0; i < 4; i++) {
        const int r = r0 + ty + i * 8, c = c0 + tx;
        const bool in = (r < RDIM && c < RDIM);
        g_Pp[r * LDS_ + c] = __float2half_rn(in ? P[(size_t)r * RDIM + c] : 0.0f);
        t[ty + i * 8][tx] = in ? Q[(size_t)r * RDIM + c] : 0.0f;
    }
    __syncthreads();
#pragma unroll
    for (int i = 0; i < 4; i++) {
        const int c = c0 + ty + i * 8, r = r0 + tx;
        g_Qt[c * LDS_ + r] = __float2half_rn(t[tx][ty + i * 8]);
    }
}

// ---------------------------------------------------------------------------
// u_b = P h_n,  v_b = Q^T h_n   (exact fp32)
// ---------------------------------------------------------------------------
__global__ void k_uv(const float* __restrict__ H, const float* __restrict__ P,
                     const float* __restrict__ Q) {
    const int b = blockIdx.x;
    const float* __restrict__ Hb = H + (size_t)b * RDIM * NCOL;
    __shared__ float hn[RDIM];
    for (int e = threadIdx.x; e < RDIM; e += blockDim.x)
        hn[e] = Hb[(size_t)e * NCOL + (NCOL - 1)];
    __syncthreads();
    for (int i = threadIdx.x; i < RDIM; i += blockDim.x) {
        float su = 0.0f, sv = 0.0f;
        for (int e = 0; e < RDIM; e++) {
            su += P[i * RDIM + e] * hn[e];
            sv += hn[e] * Q[e * RDIM + i];
        }
        g_u[b][i] = su;
        g_v[b][i] = sv;
    }
}

// ---------------------------------------------------------------------------
extern "C" void kernel_launch(void* const* d_in, const int* in_sizes, int n_in,
                              void* d_out, int out_size) {
    const float* H = (const float*)d_in[0];
    const float* P = (const float*)d_in[1];
    const float* Q = (const float*)d_in[2];
    float* out = (float*)d_out;

    cudaFuncSetAttribute(k_gemm<0>, cudaFuncAttributeMaxDynamicSharedMemorySize,
                         SMEM_BYTES);
    cudaFuncSetAttribute(k_gemm<1>, cudaFuncAttributeMaxDynamicSharedMemorySize,
                         SMEM_BYTES);
    cudaFuncSetAttribute(k_gemm<2>, cudaFuncAttributeMaxDynamicSharedMemorySize,
                         SMEM_BYTES);
    cudaFuncSetAttribute(k_gemm<3>, cudaFuncAttributeMaxDynamicSharedMemorySize,
                         SMEM_BYTES);

    __half *Hp, *Ht, *Pp, *Qt, *Gm, *Tm, *Wm;
    float* Gp;
    cudaGetSymbolAddress((void**)&Hp, g_Hp);
    cudaGetSymbolAddress((void**)&Ht, g_Ht);
    cudaGetSymbolAddress((void**)&Pp, g_Pp);
    cudaGetSymbolAddress((void**)&Qt, g_Qt);
    cudaGetSymbolAddress((void**)&Gm, g_G);
    cudaGetSymbolAddress((void**)&Tm, g_Tt);
    cudaGetSymbolAddress((void**)&Wm, g_W);
    cudaGetSymbolAddress((void**)&Gp, g_Gp);

    const size_t HPB = (size_t)MP * KHP;
    const size_t HB = (size_t)RDIM * NCOL;

    k_pad<<<dim3(KHP / 32, MP / 32, NBAT), dim3(32, 8)>>>(H);
    k_padPQ<<<dim3(12, 12), dim3(32, 8)>>>(P, Q);
    k_uv<<<NBAT, 288>>>(H, P, Q);

    // G partials = Hp (x) Hp, split-K x2 (33 chunks = 17 + 16)
    k_gemm<0><<<dim3(3, 3, NBAT * 2), 256, SMEM_BYTES>>>(
        Hp, HPB, KHP, Hp, HPB, KHP, Gp, GB_, LDS_, 0, 0, 0, nullptr, 0);
    k_reduce<<<(int)(NBAT * GB_ / 1024), 256>>>();

    // T' = Qt (x) G : K=320 (5 chunks)
    k_gemm<1><<<dim3(3, 3, NBAT), 256, SMEM_BYTES>>>(
        Qt, 0, LDS_, Gm, GB_, LDS_, Tm, GB_, LDS_, 5, 0, 0, nullptr, 0);
    // W = Pp (x) T' - u v^T
    k_gemm<2><<<dim3(3, 3, NBAT), 256, SMEM_BYTES>>>(
        Pp, 0, LDS_, Tm, GB_, LDS_, Wm, GB_, LDS_, 5, 0, 0, nullptr, 0);
    // out = H + (W (x) Htp)/n : N=2049 (17 col tiles), guarded
    k_gemm<3><<<dim3(17, 3, NBAT), 256, SMEM_BYTES>>>(
        Wm, GB_, LDS_, Ht, HPB, MP, out, HB, NCOL, 5, RDIM, NCOL, H, HB);
}

// round 7
// speedup vs baseline: 2.6311x; 1.0099x over previous
#include <cuda_runtime.h>
#include <cuda_fp16.h>
#include <cstdint>

// LinearSelfAttention via fp16-in/fp32-acc mma.sync (m16n8k16), all-NT GEMMs.
// out = H + ((P G Q - u v^T) H) / n,  G = H H^T, u = P h_n, v = Q^T h_n.
// Chain (NT: C[m,n] = sum_k A[m,k] B[n,k]):
//   G  = Hp (x) Hp       symmetric: 6 upper tiles + mirror, split-K x3
//   T' = Qt (x) G        ( = (G Q)^T )
//   W  = Pp (x) T' - u v^T
//   out= H + (W (x) Ht)/n

#define RDIM 257
#define NCOL 2049
#define NBAT 16
#define INV_N (1.0f / 2048.0f)

#define MP   384
#define KHP  2176
#define LDS_ 384
#define GB_  ((size_t)MP * LDS_)
#define HPB  ((size_t)MP * KHP)
#define HTB  ((size_t)KHP * MP)
#define HB   ((size_t)RDIM * NCOL)
#define SPLIT_ ((size_t)NBAT * GB_)

__device__ __half g_Hp[NBAT][MP * KHP];
__device__ __half g_Ht[NBAT][KHP * MP];
__device__ __half g_Pp[MP * LDS_];
__device__ __half g_Qt[MP * LDS_];
__device__ float  g_Gp[3][NBAT][MP * LDS_];   // split-K partials
__device__ __half g_G[NBAT][MP * LDS_];
__device__ __half g_Tt[NBAT][MP * LDS_];
__device__ __half g_W[NBAT][MP * LDS_];
__device__ float  g_u[NBAT][MP];              // pads stay 0
__device__ float  g_v[NBAT][MP];

// ---------------------------------------------------------------------------
__device__ __forceinline__ uint32_t smem_u32(const void* p) {
    uint32_t a;
    asm("{ .reg .u64 t; cvta.to.shared.u64 t, %1; cvt.u32.u64 %0, t; }"
        : "=r"(a) : "l"(p));
    return a;
}
__device__ __forceinline__ void cp16(void* s, const void* g) {
    uint32_t sa = smem_u32(s);
    asm volatile("cp.async.cg.shared.global [%0], [%1], 16;"
                 :: "r"(sa), "l"(g) : "memory");
}
#define CP_COMMIT() asm volatile("cp.async.commit_group;" ::: "memory")
#define CP_WAIT1()  asm volatile("cp.async.wait_group 1;" ::: "memory")
#define CP_WAIT2()  asm volatile("cp.async.wait_group 2;" ::: "memory")

__device__ __forceinline__ void mma16(float* c, const uint32_t* a,
                                      const uint32_t* b) {
    asm volatile(
        "mma.sync.aligned.m16n8k16.row.col.f32.f16.f16.f32 "
        "{%0,%1,%2,%3}, {%4,%5,%6,%7}, {%8,%9}, {%0,%1,%2,%3};"
        : "+f"(c[0]), "+f"(c[1]), "+f"(c[2]), "+f"(c[3])
        : "r"(a[0]), "r"(a[1]), "r"(a[2]), "r"(a[3]), "r"(b[0]), "r"(b[1]));
}

// ---------------------------------------------------------------------------
// Stage 1: G partials = Hp (x) Hp, symmetric, split-K x3, BK=64, depth-2.
// grid (6, 1, NBAT*3), block 256, smem 4*128*72*2 = 73728 B.
// ---------------------------------------------------------------------------
#define ABUF64 (128 * 72)
#define SMEM_SYRK (4 * ABUF64 * 2)

__device__ __forceinline__ void load64(__half* dst, const __half* __restrict__ g,
                                       int ld, int r0, int k0, int tid) {
    const __half* gp = g + (size_t)r0 * ld + k0;
    const int kk = (tid & 7) * 8;
    const int r = tid >> 3;
#pragma unroll
    for (int i = 0; i < 4; i++)
        cp16(dst + (r + i * 32) * 72 + kk, gp + (size_t)(r + i * 32) * ld + kk);
}

__global__ void __launch_bounds__(256, 2) k_syrk() {
    extern __shared__ __half sm[];
    __half* As = sm;
    __half* Bs = sm + 2 * ABUF64;

    const int tid = threadIdx.x;
    const int b = blockIdx.z / 3;
    const int sp = blockIdx.z % 3;
    const int TI[6] = {0, 0, 0, 1, 1, 2};
    const int TJ[6] = {0, 1, 2, 1, 2, 2};
    const int ti = TI[blockIdx.x], tj = TJ[blockIdx.x];
    const int m0 = ti * 128, n0 = tj * 128;
    const int c0 = sp * 11;

    const __half* Hb = g_Hp[b];
    float* Cf = &g_Gp[sp][b][0];

    const int lane = tid & 31, wid = tid >> 5;
    const int wm = (wid & 3) * 32;
    const int wn = (wid >> 2) * 64;
    const int g = lane >> 2, tg = lane & 3;

    float acc[2][8][4];
#pragma unroll
    for (int i = 0; i < 2; i++)
#pragma unroll
        for (int j = 0; j < 8; j++)
#pragma unroll
            for (int r = 0; r < 4; r++) acc[i][j][r] = 0.0f;

    load64(As, Hb, KHP, m0, c0 * 64, tid);
    load64(Bs, Hb, KHP, n0, c0 * 64, tid);
    CP_COMMIT();

    for (int c = 0; c < 11; c++) {
        if (c + 1 < 11) {
            const int nb = (c + 1) & 1;
            const int k0 = (c0 + c + 1) * 64;
            load64(As + nb * ABUF64, Hb, KHP, m0, k0, tid);
            load64(Bs + nb * ABUF64, Hb, KHP, n0, k0, tid);
        }
        CP_COMMIT();
        CP_WAIT1();
        __syncthreads();

        const __half* As_ = As + (c & 1) * ABUF64;
        const __half* Bs_ = Bs + (c & 1) * ABUF64;
#pragma unroll
        for (int ks = 0; ks < 4; ks++) {
            const int k = ks * 16;
            uint32_t a[2][4], bf[8][2];
#pragma unroll
            for (int mt = 0; mt < 2; mt++) {
                const int r = wm + mt * 16 + g;
                a[mt][0] = *(const uint32_t*)&As_[r * 72 + k + 2 * tg];
                a[mt][1] = *(const uint32_t*)&As_[(r + 8) * 72 + k + 2 * tg];
                a[mt][2] = *(const uint32_t*)&As_[r * 72 + k + 2 * tg + 8];
                a[mt][3] = *(const uint32_t*)&As_[(r + 8) * 72 + k + 2 * tg + 8];
            }
#pragma unroll
            for (int nt = 0; nt < 8; nt++) {
                const int cn = wn + nt * 8 + g;
                bf[nt][0] = *(const uint32_t*)&Bs_[cn * 72 + k + 2 * tg];
                bf[nt][1] = *(const uint32_t*)&Bs_[cn * 72 + k + 2 * tg + 8];
            }
#pragma unroll
            for (int mt = 0; mt < 2; mt++)
#pragma unroll
                for (int nt = 0; nt < 8; nt++) mma16(acc[mt][nt], a[mt], bf[nt]);
        }
        __syncthreads();
    }

    // epilogue: own tile (float2) + mirror for off-diagonal tiles
#pragma unroll
    for (int mt = 0; mt < 2; mt++) {
#pragma unroll
        for (int half = 0; half < 2; half++) {
            const int row = m0 + wm + mt * 16 + g + half * 8;
#pragma unroll
            for (int nt = 0; nt < 8; nt++) {
                const int col = n0 + wn + nt * 8 + tg * 2;
                const float v0 = acc[mt][nt][half * 2 + 0];
                const float v1 = acc[mt][nt][half * 2 + 1];
                float2 st = {v0, v1};
                *(float2*)&Cf[(size_t)row * LDS_ + col] = st;
                if (ti != tj) {
                    Cf[(size_t)col * LDS_ + row] = v0;
                    Cf[(size_t)(col + 1) * LDS_ + row] = v1;
                }
            }
        }
    }
}

// ---------------------------------------------------------------------------
// reduce: G fp16 = p0 + p1 + p2
// ---------------------------------------------------------------------------
__global__ void k_reduce() {
    const size_t i = ((size_t)blockIdx.x * 256 + threadIdx.x) * 4;
    const float* p0 = &g_Gp[0][0][0];
    const float* p1 = &g_Gp[1][0][0];
    const float* p2 = &g_Gp[2][0][0];
    __half* o = &g_G[0][0];
    float4 x = *(const float4*)(p0 + i);
    float4 y = *(const float4*)(p1 + i);
    float4 z = *(const float4*)(p2 + i);
    *(__half2*)(o + i) = __floats2half2_rn(x.x + y.x + z.x, x.y + y.y + z.y);
    *(__half2*)(o + i + 2) = __floats2half2_rn(x.z + y.z + z.z, x.w + y.w + z.w);
}

// ---------------------------------------------------------------------------
// Small-K GEMMs: BK=32, depth-3 pipeline, 9 chunks (K=288).
//  MODE 1: T' = Qt (x) G          -> fp16
//  MODE 2: W  = Pp (x) T' - uv^T  -> fp16
//  MODE 3: out= H + (W (x) Ht)/n  -> fp32, guarded
// ---------------------------------------------------------------------------
#define ABUF32 (128 * 40)
#define SMEM_G32 (6 * ABUF32 * 2)   // 61440 B

__device__ __forceinline__ void load32(__half* dst, const __half* __restrict__ g,
                                       int ld, int r0, int k0, int tid) {
    const __half* gp = g + (size_t)r0 * ld + k0;
    const int kk = (tid & 3) * 8;
    const int r = tid >> 2;
    cp16(dst + r * 40 + kk, gp + (size_t)r * ld + kk);
    cp16(dst + (r + 64) * 40 + kk, gp + (size_t)(r + 64) * ld + kk);
}

template <int MODE>
__global__ void __launch_bounds__(256, 2)
k_gemm32(const __half* __restrict__ A, size_t sA, int lda,
         const __half* __restrict__ B, size_t sB, int ldb,
         void* __restrict__ Cv, size_t sC, int ldc,
         const float* __restrict__ E, size_t sE) {
    extern __shared__ __half sm[];
    __half* As = sm;                 // 3 buffers
    __half* Bs = sm + 3 * ABUF32;    // 3 buffers

    const int tid = threadIdx.x;
    const int b = blockIdx.z;
    const int m0 = blockIdx.y * 128, n0 = blockIdx.x * 128;
    const __half* Ab = A + (size_t)b * sA;
    const __half* Bb = B + (size_t)b * sB;

    const int lane = tid & 31, wid = tid >> 5;
    const int wm = (wid & 3) * 32;
    const int wn = (wid >> 2) * 64;
    const int g = lane >> 2, tg = lane & 3;

    float acc[2][8][4];
#pragma unroll
    for (int i = 0; i < 2; i++)
#pragma unroll
        for (int j = 0; j < 8; j++)
#pragma unroll
            for (int r = 0; r < 4; r++) acc[i][j][r] = 0.0f;

    // prologue: chunks 0,1
    load32(As, Ab, lda, m0, 0, tid);
    load32(Bs, Bb, ldb, n0, 0, tid);
    CP_COMMIT();
    load32(As + ABUF32, Ab, lda, m0, 32, tid);
    load32(Bs + ABUF32, Bb, ldb, n0, 32, tid);
    CP_COMMIT();

    for (int c = 0; c < 9; c++) {
        if (c + 2 < 9) {
            const int nb = (c + 2) % 3;
            const int k0 = (c + 2) * 32;
            load32(As + nb * ABUF32, Ab, lda, m0, k0, tid);
            load32(Bs + nb * ABUF32, Bb, ldb, n0, k0, tid);
        }
        CP_COMMIT();
        CP_WAIT2();
        __syncthreads();

        const __half* As_ = As + (c % 3) * ABUF32;
        const __half* Bs_ = Bs + (c % 3) * ABUF32;
#pragma unroll
        for (int ks = 0; ks < 2; ks++) {
            const int k = ks * 16;
            uint32_t a[2][4], bf[8][2];
#pragma unroll
            for (int mt = 0; mt < 2; mt++) {
                const int r = wm + mt * 16 + g;
                a[mt][0] = *(const uint32_t*)&As_[r * 40 + k + 2 * tg];
                a[mt][1] = *(const uint32_t*)&As_[(r + 8) * 40 + k + 2 * tg];
                a[mt][2] = *(const uint32_t*)&As_[r * 40 + k + 2 * tg + 8];
                a[mt][3] = *(const uint32_t*)&As_[(r + 8) * 40 + k + 2 * tg + 8];
            }
#pragma unroll
            for (int nt = 0; nt < 8; nt++) {
                const int cn = wn + nt * 8 + g;
                bf[nt][0] = *(const uint32_t*)&Bs_[cn * 40 + k + 2 * tg];
                bf[nt][1] = *(const uint32_t*)&Bs_[cn * 40 + k + 2 * tg + 8];
            }
#pragma unroll
            for (int mt = 0; mt < 2; mt++)
#pragma unroll
                for (int nt = 0; nt < 8; nt++) mma16(acc[mt][nt], a[mt], bf[nt]);
        }
        __syncthreads();
    }

    // epilogue
#pragma unroll
    for (int mt = 0; mt < 2; mt++) {
#pragma unroll
        for (int half = 0; half < 2; half++) {
            const int row = m0 + wm + mt * 16 + g + half * 8;
            if (MODE == 3 && row >= RDIM) continue;
            float uu = 0.0f;
            if (MODE == 2) uu = g_u[b][row];
#pragma unroll
            for (int nt = 0; nt < 8; nt++) {
                const int col = n0 + wn + nt * 8 + tg * 2;
                float v0 = acc[mt][nt][half * 2 + 0];
                float v1 = acc[mt][nt][half * 2 + 1];
                if (MODE == 1) {
                    __half* Ch = (__half*)Cv + (size_t)b * sC;
                    *(__half2*)&Ch[(size_t)row * ldc + col] =
                        __floats2half2_rn(v0, v1);
                } else if (MODE == 2) {
                    __half* Ch = (__half*)Cv + (size_t)b * sC;
                    v0 -= uu * g_v[b][col];
                    v1 -= uu * g_v[b][col + 1];
                    *(__half2*)&Ch[(size_t)row * ldc + col] =
                        __floats2half2_rn(v0, v1);
                } else {
                    float* Cf = (float*)Cv + (size_t)b * sC;
                    const float* Eb = E + (size_t)b * sE;
                    const size_t idx = (size_t)row * ldc + col;
                    if (col < NCOL) Cf[idx] = Eb[idx] + v0 * INV_N;
                    if (col + 1 < NCOL) Cf[idx + 1] = Eb[idx + 1] + v1 * INV_N;
                }
            }
        }
    }
}

// ---------------------------------------------------------------------------
// fused setup: z<16 padH(batch z); z==16 padPQ; z==17 uv.
// grid (34, 12, 18), block 256.
// ---------------------------------------------------------------------------
__global__ void k_setup(const float* __restrict__ H, const float* __restrict__ P,
                        const float* __restrict__ Q) {
    __shared__ float t[32][65];
    const int tid = threadIdx.x;
    const int z = blockIdx.z;

    if (z < NBAT) {
        // padH: tile 32 d-rows x 64 t-cols -> Hp (half2) and Ht (half2)
        const int b = z;
        const int c0 = blockIdx.x * 64;
        const int r0 = blockIdx.y * 32;
        const float* Hb = H + (size_t)b * HB;
        const int tx = tid & 31, ty = tid >> 5;
#pragma unroll
        for (int i = 0; i < 4; i++) {
            const int r = r0 + ty + i * 8;
            const int c = c0 + 2 * tx;
            float v0 = 0.0f, v1 = 0.0f;
            if (r < RDIM) {
                if (c < NCOL) v0 = Hb[(size_t)r * NCOL + c];
                if (c + 1 < NCOL) v1 = Hb[(size_t)r * NCOL + c + 1];
            }
            t[ty + i * 8][2 * tx] = v0;
            t[ty + i * 8][2 * tx + 1] = v1;
            *(__half2*)&g_Hp[b][(size_t)r * KHP + c] = __floats2half2_rn(v0, v1);
        }
        __syncthreads();
#pragma unroll
        for (int i = 0; i < 4; i++) {
            const int cl = tid >> 2;
            const int pr = (tid & 3) + 4 * i;
            const float v0 = t[2 * pr][cl];
            const float v1 = t[2 * pr + 1][cl];
            *(__half2*)&g_Ht[b][(size_t)(c0 + cl) * MP + r0 + 2 * pr] =
                __floats2half2_rn(v0, v1);
        }
    } else if (z == NBAT) {
        // padPQ: 32x32 tile -> Pp[r][c], Qt[c][r]
        if (blockIdx.x >= 12) return;
        const int c0 = blockIdx.x * 32, r0 = blockIdx.y * 32;
        const int tx = tid & 31, ty = tid >> 5;
#pragma unroll
        for (int i = 0; i < 4; i++) {
            const int r = r0 + ty + i * 8, c = c0 + tx;
            const bool in = (r < RDIM && c < RDIM);
            g_Pp[(size_t)r * LDS_ + c] =
                __float2half_rn(in ? P[(size_t)r * RDIM + c] : 0.0f);
            t[ty + i * 8][tx] = in ? Q[(size_t)r * RDIM + c] : 0.0f;
        }
        __syncthreads();
#pragma unroll
        for (int i = 0; i < 4; i++) {
            const int c = c0 + ty + i * 8, r = r0 + tx;
            g_Qt[(size_t)c * LDS_ + r] = __float2half_rn(t[tx][ty + i * 8]);
        }
    } else {
        // uv: u_b = P h_n, v_b = Q^T h_n (exact fp32)
        if (blockIdx.x >= NBAT || blockIdx.y != 0) return;
        const int b = blockIdx.x;
        const float* Hb = H + (size_t)b * HB;
        __shared__ float hn[RDIM];
        for (int e = tid; e < RDIM; e += 256)
            hn[e] = Hb[(size_t)e * NCOL + (NCOL - 1)];
        __syncthreads();
        for (int i = tid; i < RDIM; i += 256) {
            float su = 0.0f, sv = 0.0f;
            for (int e = 0; e < RDIM; e++) {
                su += P[(size_t)i * RDIM + e] * hn[e];
                sv += hn[e] * Q[(size_t)e * RDIM + i];
            }
            g_u[b][i] = su;
            g_v[b][i] = sv;
        }
    }
}

// ---------------------------------------------------------------------------
extern "C" void kernel_launch(void* const* d_in, const int* in_sizes, int n_in,
                              void* d_out, int out_size) {
    const float* H = (const float*)d_in[0];
    const float* P = (const float*)d_in[1];
    const float* Q = (const float*)d_in[2];
    float* out = (float*)d_out;

    cudaFuncSetAttribute(k_syrk, cudaFuncAttributeMaxDynamicSharedMemorySize,
                         SMEM_SYRK);
    cudaFuncSetAttribute(k_gemm32<1>,
                         cudaFuncAttributeMaxDynamicSharedMemorySize, SMEM_G32);
    cudaFuncSetAttribute(k_gemm32<2>,
                         cudaFuncAttributeMaxDynamicSharedMemorySize, SMEM_G32);
    cudaFuncSetAttribute(k_gemm32<3>,
                         cudaFuncAttributeMaxDynamicSharedMemorySize, SMEM_G32);

    __half *Ht, *Pp, *Qt, *Gm, *Tm, *Wm;
    cudaGetSymbolAddress((void**)&Ht, g_Ht);
    cudaGetSymbolAddress((void**)&Pp, g_Pp);
    cudaGetSymbolAddress((void**)&Qt, g_Qt);
    cudaGetSymbolAddress((void**)&Gm, g_G);
    cudaGetSymbolAddress((void**)&Tm, g_Tt);
    cudaGetSymbolAddress((void**)&Wm, g_W);

    // 1) setup: pad H -> Hp/Ht, pad P/Q^T, compute u/v
    k_setup<<<dim3(34, 12, NBAT + 2), 256>>>(H, P, Q);
    // 2) G partials (symmetric, split-K x3)
    k_syrk<<<dim3(6, 1, NBAT * 3), 256, SMEM_SYRK>>>();
    // 3) G = sum partials -> fp16
    k_reduce<<<(int)(NBAT * GB_ / 1024), 256>>>();
    // 4) T' = Qt (x) G
    k_gemm32<1><<<dim3(3, 3, NBAT), 256, SMEM_G32>>>(
        Qt, 0, LDS_, Gm, GB_, LDS_, Tm, GB_, LDS_, nullptr, 0);
    // 5) W = Pp (x) T' - u v^T
    k_gemm32<2><<<dim3(3, 3, NBAT), 256, SMEM_G32>>>(
        Pp, 0, LDS_, Tm, GB_, LDS_, Wm, GB_, LDS_, nullptr, 0);
    // 6) out = H + (W (x) Ht)/n
    k_gemm32<3><<<dim3(17, 3, NBAT), 256, SMEM_G32>>>(
        Wm, GB_, LDS_, Ht, HTB, MP, out, HB, NCOL, H, HB);
}